// round 14
// baseline (speedup 1.0000x reference)
#include <cuda_runtime.h>
#include <cuda_bf16.h>
#include <math.h>
#include <stdint.h>

#define BATCH 8192
#define CH 128
#define NB 32
#define NH 4
#define O3 384
#define ATT_SCALE 0.17677669529663687f  // 1/sqrt(32)

__device__ __forceinline__ uint32_t smem_u32(const void* p) {
    uint32_t a;
    asm("{ .reg .u64 t; cvta.to.shared.u64 t, %1; cvt.u32.u64 %0, t; }" : "=r"(a) : "l"(p));
    return a;
}
__device__ __forceinline__ void mma_a(float* acc, const uint32_t* a, uint32_t b0, uint32_t b1) {
    asm volatile(
        "mma.sync.aligned.m16n8k16.row.col.f32.bf16.bf16.f32 "
        "{%0,%1,%2,%3}, {%4,%5,%6,%7}, {%8,%9}, {%0,%1,%2,%3};"
        : "+f"(acc[0]), "+f"(acc[1]), "+f"(acc[2]), "+f"(acc[3])
        : "r"(a[0]), "r"(a[1]), "r"(a[2]), "r"(a[3]), "r"(b0), "r"(b1));
}
__device__ __forceinline__ uint32_t cvtbf2(float hi, float lo) {
    uint32_t r; asm("cvt.rn.bf16x2.f32 %0, %1, %2;" : "=r"(r) : "f"(hi), "f"(lo)); return r;
}
__device__ __forceinline__ float bf_lo_f(uint32_t w) { return __uint_as_float(w << 16); }
__device__ __forceinline__ float bf_hi_f(uint32_t w) { return __uint_as_float(w & 0xffff0000u); }
#define LDSM_X4(r0,r1,r2,r3,addr) \
    asm volatile("ldmatrix.sync.aligned.m8n8.x4.shared.b16 {%0,%1,%2,%3}, [%4];" \
        : "=r"(r0), "=r"(r1), "=r"(r2), "=r"(r3) : "r"(addr))
#define LDSM_X4T(r0,r1,r2,r3,addr) \
    asm volatile("ldmatrix.sync.aligned.m8n8.x4.trans.shared.b16 {%0,%1,%2,%3}, [%4];" \
        : "=r"(r0), "=r"(r1), "=r"(r2), "=r"(r3) : "r"(addr))

// ---- device scratch ----
__device__ uint4  g_wfrag[2 * 24 * 8 * 32];   // qkv_w fragments [term][mt][ks][lane]
__device__ uint4  g_ofrag[2 * 8 * 8 * 32];    // out_w fragments
__device__ double g_bn_sum[CH];
__device__ double g_bn_sqs[CH];
__device__ float  g_bn_g[CH];
__device__ float  g_bn_b[CH];

__device__ __forceinline__ uint32_t bf16pair(float w0, float w1, int lo_term) {
    __nv_bfloat16 h0 = __float2bfloat16_rn(w0);
    __nv_bfloat16 h1 = __float2bfloat16_rn(w1);
    if (lo_term) {
        h0 = __float2bfloat16_rn(w0 - __bfloat162float(h0));
        h1 = __float2bfloat16_rn(w1 - __bfloat162float(h1));
    }
    return ((uint32_t)__bfloat16_as_ushort(h1) << 16) | __bfloat16_as_ushort(h0);
}

__global__ void prep_kernel(const float* __restrict__ qkv_w,
                            const float* __restrict__ out_w) {
    int i = blockIdx.x * blockDim.x + threadIdx.x;
    if (i < 2 * 24 * 8 * 32) {
        int lane = i & 31, ks = (i >> 5) & 7, mt = (i >> 8) % 24, term = i / (24 * 8 * 32);
        int g = lane >> 2, cg = lane & 3;
        int r0 = mt * 16 + g, r1 = r0 + 8;
        int c0 = ks * 16 + 2 * cg, c1 = c0 + 8;
        uint4 f;
        f.x = bf16pair(qkv_w[r0 * CH + c0], qkv_w[r0 * CH + c0 + 1], term);
        f.y = bf16pair(qkv_w[r1 * CH + c0], qkv_w[r1 * CH + c0 + 1], term);
        f.z = bf16pair(qkv_w[r0 * CH + c1], qkv_w[r0 * CH + c1 + 1], term);
        f.w = bf16pair(qkv_w[r1 * CH + c1], qkv_w[r1 * CH + c1 + 1], term);
        g_wfrag[i] = f;
    }
    if (i < 2 * 8 * 8 * 32) {
        int lane = i & 31, ks = (i >> 5) & 7, mt = (i >> 8) & 7, term = i / (8 * 8 * 32);
        int g = lane >> 2, cg = lane & 3;
        int r0 = mt * 16 + g, r1 = r0 + 8;
        int c0 = ks * 16 + 2 * cg, c1 = c0 + 8;
        uint4 f;
        f.x = bf16pair(out_w[r0 * CH + c0], out_w[r0 * CH + c0 + 1], term);
        f.y = bf16pair(out_w[r1 * CH + c0], out_w[r1 * CH + c0 + 1], term);
        f.z = bf16pair(out_w[r0 * CH + c1], out_w[r0 * CH + c1 + 1], term);
        f.w = bf16pair(out_w[r1 * CH + c1], out_w[r1 * CH + c1 + 1], term);
        g_ofrag[i] = f;
    }
    if (i < CH) { g_bn_sum[i] = 0.0; g_bn_sqs[i] = 0.0; }
}

// smem (bytes): region0 x/ao hi/lo tiles [32][136]bf16 (A -> C/D);
// qkvt qh,ql,kh,kl,vh,vl each [128][32]bf16 @ 18432; rp @ 67584.
#define XLO_BYTE 8704
#define XROW_B   272
#define QT_BYTE  18432
#define MATK     16384
#define MATV     32768
#define LO_OFF   8192
#define RP_FLOAT 16896
#define SMEM_FLOATS 17152

__global__ void __launch_bounds__(128, 3)
attn_kernel(const float* __restrict__ x,
            const float* __restrict__ qkv_b,
            const float* __restrict__ out_b,
            const float* __restrict__ remb,
            float* __restrict__ out) {
    extern __shared__ float sm[];
    float* rp = sm + RP_FLOAT;

    const int tid  = threadIdx.x;
    const int lane = tid & 31;
    const int wid  = tid >> 5;
    const int b    = blockIdx.x;
    const float* xb = x + (size_t)b * (CH * NB);
    float* ob2g = out + (size_t)b * (CH * NB);

    const int g  = lane >> 2, tg = lane & 3, cg = tg;
    const int sub = lane >> 3, i7 = lane & 7;
    const int ntb = ((sub >> 1) & 1) * 8 + i7;   // plain ldmatrix row offset
    const int khb = (sub & 1) * 16;              // plain ldmatrix byte-col offset
    const int qa_d = ((sub >> 1) & 1) * 8 + i7;  // trans-A source row (d)
    const int qa_n = (sub & 1) * 8;
    const int kb_d = (sub & 1) * 8 + i7;         // trans-B source row (d)
    const int kb_m = ((sub >> 1) & 1) * 8;

    const uint32_t SB = smem_u32(sm);

    // ---- packed xconv: row pairs (c,c+1) -> u32 bf16x2 stores ----
    {
        char* ah = (char*)sm;
        char* al = (char*)sm + XLO_BYTE;
#pragma unroll
        for (int it = 0; it < 4; it++) {
            int idx = tid + it * 128;            // pair index 0..511
            int cp = idx >> 3;                   // c pair 0..63
            int n0 = (idx & 7) * 4;
            int c = cp * 2;
            float4 va = *(const float4*)(xb + c * 32 + n0);
            float4 vb = *(const float4*)(xb + (c + 1) * 32 + n0);
            float a4[4] = {va.x, va.y, va.z, va.w};
            float b4[4] = {vb.x, vb.y, vb.z, vb.w};
#pragma unroll
            for (int j = 0; j < 4; j++) {
                uint32_t h = cvtbf2(b4[j], a4[j]);
                *(uint32_t*)(ah + (n0 + j) * XROW_B + c * 2) = h;
                uint32_t l = cvtbf2(b4[j] - bf_hi_f(h), a4[j] - bf_lo_f(h));
                *(uint32_t*)(al + (n0 + j) * XROW_B + c * 2) = l;
            }
        }
    }
    for (int i = tid; i < (2 * NB - 1) * NH; i += 128) {
        int p = i >> 2, h = i & 3;
        rp[h * 63 + p] = remb[i];
    }
    __syncthreads();

    // ---- Phase A: qkv = W @ x ; 3-mt blocks share B fragments ----
    {
        const uint32_t xhi_u32 = SB, xlo_u32 = SB + XLO_BYTE;
#pragma unroll
        for (int blk = 0; blk < 2; blk++) {
            float acc[3][16];
#pragma unroll
            for (int m = 0; m < 3; m++)
#pragma unroll
                for (int j = 0; j < 16; j++) acc[m][j] = 0.0f;
#pragma unroll
            for (int term = 0; term < 3; term++) {
                const int termA = (term == 2) ? 1 : 0;
                const uint32_t xbase = (term == 1) ? xlo_u32 : xhi_u32;
#pragma unroll
                for (int ks = 0; ks < 8; ks++) {
                    uint32_t baddr = xbase + ntb * XROW_B + ks * 32 + khb;
                    uint32_t b0, b1, b2, b3, b4, b5, b6, b7;
                    LDSM_X4(b0, b1, b2, b3, baddr);
                    LDSM_X4(b4, b5, b6, b7, baddr + 16 * XROW_B);
#pragma unroll
                    for (int m = 0; m < 3; m++) {
                        int mt = wid * 6 + blk * 3 + m;
                        uint4 a = g_wfrag[((termA * 24 + mt) * 8 + ks) * 32 + lane];
                        uint32_t au[4] = {a.x, a.y, a.z, a.w};
                        mma_a(acc[m] + 0,  au, b0, b1);
                        mma_a(acc[m] + 4,  au, b2, b3);
                        mma_a(acc[m] + 8,  au, b4, b5);
                        mma_a(acc[m] + 12, au, b6, b7);
                    }
                }
            }
#pragma unroll
            for (int m = 0; m < 3; m++) {
                int mt = wid * 6 + blk * 3 + m;
                int r0 = mt * 16 + g, r1 = r0 + 8;
                float bias0 = qkv_b[r0], bias1 = qkv_b[r1];
                int mat = r0 >> 7;
                char* hb0 = (char*)sm + QT_BYTE + mat * 16384 + (r0 & 127) * 64;
                char* hb1 = (char*)sm + QT_BYTE + mat * 16384 + (r1 & 127) * 64;
#pragma unroll
                for (int nt = 0; nt < 4; nt++) {
                    int nc2 = (nt * 8 + 2 * cg) * 2;
                    float v00 = acc[m][nt*4+0] + bias0, v01 = acc[m][nt*4+1] + bias0;
                    float v10 = acc[m][nt*4+2] + bias1, v11 = acc[m][nt*4+3] + bias1;
                    uint32_t h0 = cvtbf2(v01, v00);
                    uint32_t h1 = cvtbf2(v11, v10);
                    *(uint32_t*)(hb0 + nc2) = h0;
                    *(uint32_t*)(hb1 + nc2) = h1;
                    uint32_t l0 = cvtbf2(v01 - bf_hi_f(h0), v00 - bf_lo_f(h0));
                    uint32_t l1 = cvtbf2(v11 - bf_hi_f(h1), v10 - bf_lo_f(h1));
                    *(uint32_t*)(hb0 + LO_OFF + nc2) = l0;
                    *(uint32_t*)(hb1 + LO_OFF + nc2) = l1;
                }
            }
        }
    }
    __syncthreads();   // qkv tiles ready; x tiles dead

    // ---- Phase B: S = Q^T K per head (3-term) ----
    float sa[2][4][4];
#pragma unroll
    for (int a1 = 0; a1 < 2; a1++)
#pragma unroll
        for (int a2 = 0; a2 < 4; a2++)
#pragma unroll
            for (int a3 = 0; a3 < 4; a3++) sa[a1][a2][a3] = 0.0f;
    {
        const int dgb = wid * 32;
        const uint32_t qb0 = SB + QT_BYTE;
        const uint32_t kb0 = SB + QT_BYTE + MATK;
#pragma unroll
        for (int term = 0; term < 3; term++) {
            const uint32_t qm = qb0 + ((term == 2) ? LO_OFF : 0);
            const uint32_t km = kb0 + ((term == 1) ? LO_OFF : 0);
#pragma unroll
            for (int kb = 0; kb < 32; kb += 16) {
                uint32_t aQ[2][4], bK[2][4];
#pragma unroll
                for (int nb2 = 0; nb2 < 2; nb2++) {
                    uint32_t ad = qm + (dgb + kb + qa_d) * 64 + (nb2 * 16 + qa_n) * 2;
                    LDSM_X4T(aQ[nb2][0], aQ[nb2][1], aQ[nb2][2], aQ[nb2][3], ad);
                }
#pragma unroll
                for (int mb2 = 0; mb2 < 2; mb2++) {
                    uint32_t ad = km + (dgb + kb + kb_d) * 64 + (mb2 * 16 + kb_m) * 2;
                    LDSM_X4T(bK[mb2][0], bK[mb2][1], bK[mb2][2], bK[mb2][3], ad);
                }
#pragma unroll
                for (int nb = 0; nb < 2; nb++) {
                    mma_a(sa[nb][0], aQ[nb], bK[0][0], bK[0][1]);
                    mma_a(sa[nb][1], aQ[nb], bK[0][2], bK[0][3]);
                    mma_a(sa[nb][2], aQ[nb], bK[1][0], bK[1][1]);
                    mma_a(sa[nb][3], aQ[nb], bK[1][2], bK[1][3]);
                }
            }
        }
    }

    // ---- softmax on fragments ----
    {
#pragma unroll
        for (int nb = 0; nb < 2; nb++)
#pragma unroll
            for (int nt = 0; nt < 4; nt++)
#pragma unroll
                for (int j = 0; j < 4; j++) {
                    int row = nb * 16 + g + (j >> 1) * 8;
                    int m = nt * 8 + 2 * tg + (j & 1);
                    sa[nb][nt][j] = fmaf(sa[nb][nt][j], ATT_SCALE,
                                         rp[wid * 63 + (m - row + NB - 1)]);
                }
        float mx[4], sme[4];
#pragma unroll
        for (int k = 0; k < 4; k++) {
            int nb = k >> 1, jo = (k & 1) * 2;
            float m0 = -1e30f;
#pragma unroll
            for (int nt = 0; nt < 4; nt++)
                m0 = fmaxf(m0, fmaxf(sa[nb][nt][jo], sa[nb][nt][jo + 1]));
            mx[k] = m0;
        }
#pragma unroll
        for (int k = 0; k < 4; k++) {
            mx[k] = fmaxf(mx[k], __shfl_xor_sync(0xffffffffu, mx[k], 1));
            mx[k] = fmaxf(mx[k], __shfl_xor_sync(0xffffffffu, mx[k], 2));
        }
#pragma unroll
        for (int k = 0; k < 4; k++) {
            int nb = k >> 1, jo = (k & 1) * 2;
            float s = 0.0f;
#pragma unroll
            for (int nt = 0; nt < 4; nt++) {
                float e0 = __expf(sa[nb][nt][jo]     - mx[k]);
                float e1 = __expf(sa[nb][nt][jo + 1] - mx[k]);
                sa[nb][nt][jo] = e0; sa[nb][nt][jo + 1] = e1;
                s += e0 + e1;
            }
            sme[k] = s;
        }
#pragma unroll
        for (int k = 0; k < 4; k++) {
            sme[k] += __shfl_xor_sync(0xffffffffu, sme[k], 1);
            sme[k] += __shfl_xor_sync(0xffffffffu, sme[k], 2);
            sme[k] = 1.0f / sme[k];
        }
#pragma unroll
        for (int k = 0; k < 4; k++) {
            int nb = k >> 1, jo = (k & 1) * 2;
#pragma unroll
            for (int nt = 0; nt < 4; nt++) {
                sa[nb][nt][jo]     *= sme[k];
                sa[nb][nt][jo + 1] *= sme[k];
            }
        }
    }

    // ---- Phase C: O = P V ; P fragments direct (hi/lo split) ----
    {
        uint32_t ph[2][2][4], pl[2][2][4];
#pragma unroll
        for (int nb = 0; nb < 2; nb++)
#pragma unroll
            for (int mk = 0; mk < 2; mk++) {
                const float* p0 = sa[nb][2 * mk];
                const float* p1 = sa[nb][2 * mk + 1];
                uint32_t h;
                h = cvtbf2(p0[1], p0[0]); ph[nb][mk][0] = h;
                pl[nb][mk][0] = cvtbf2(p0[1] - bf_hi_f(h), p0[0] - bf_lo_f(h));
                h = cvtbf2(p0[3], p0[2]); ph[nb][mk][1] = h;
                pl[nb][mk][1] = cvtbf2(p0[3] - bf_hi_f(h), p0[2] - bf_lo_f(h));
                h = cvtbf2(p1[1], p1[0]); ph[nb][mk][2] = h;
                pl[nb][mk][2] = cvtbf2(p1[1] - bf_hi_f(h), p1[0] - bf_lo_f(h));
                h = cvtbf2(p1[3], p1[2]); ph[nb][mk][3] = h;
                pl[nb][mk][3] = cvtbf2(p1[3] - bf_hi_f(h), p1[2] - bf_lo_f(h));
            }
        float oa[2][4][4];
#pragma unroll
        for (int a1 = 0; a1 < 2; a1++)
#pragma unroll
            for (int a2 = 0; a2 < 4; a2++)
#pragma unroll
                for (int a3 = 0; a3 < 4; a3++) oa[a1][a2][a3] = 0.0f;

        const int dgb = wid * 32;
        const uint32_t vb0 = SB + QT_BYTE + MATV;
#pragma unroll
        for (int term = 0; term < 3; term++) {
            const int useL = (term == 2);
            const uint32_t vm = vb0 + ((term == 1) ? LO_OFF : 0);
#pragma unroll
            for (int mk = 0; mk < 2; mk++) {
                uint32_t bV[2][4];
#pragma unroll
                for (int dvb = 0; dvb < 2; dvb++) {
                    uint32_t ad = vm + (dgb + dvb * 16 + ntb) * 64 + mk * 32 + khb;
                    LDSM_X4(bV[dvb][0], bV[dvb][1], bV[dvb][2], bV[dvb][3], ad);
                }
#pragma unroll
                for (int nb = 0; nb < 2; nb++) {
                    const uint32_t* ap = useL ? pl[nb][mk] : ph[nb][mk];
                    mma_a(oa[nb][0], ap, bV[0][0], bV[0][1]);
                    mma_a(oa[nb][1], ap, bV[0][2], bV[0][3]);
                    mma_a(oa[nb][2], ap, bV[1][0], bV[1][1]);
                    mma_a(oa[nb][3], ap, bV[1][2], bV[1][3]);
                }
            }
        }
        // write ao bf16 hi/lo tiles [n][136] into region0 (x tiles dead)
        char* ah = (char*)sm;
        char* al = (char*)sm + XLO_BYTE;
#pragma unroll
        for (int nb = 0; nb < 2; nb++)
#pragma unroll
            for (int dvt = 0; dvt < 4; dvt++) {
                int row0 = nb * 16 + g, row1 = row0 + 8;
                int colb = (wid * 32 + dvt * 8 + 2 * tg) * 2;
                float d0 = oa[nb][dvt][0], d1 = oa[nb][dvt][1];
                float d2 = oa[nb][dvt][2], d3 = oa[nb][dvt][3];
                uint32_t h0 = cvtbf2(d1, d0), h1 = cvtbf2(d3, d2);
                *(uint32_t*)(ah + row0 * XROW_B + colb) = h0;
                *(uint32_t*)(ah + row1 * XROW_B + colb) = h1;
                uint32_t l0 = cvtbf2(d1 - bf_hi_f(h0), d0 - bf_lo_f(h0));
                uint32_t l1 = cvtbf2(d3 - bf_hi_f(h1), d2 - bf_lo_f(h1));
                *(uint32_t*)(al + row0 * XROW_B + colb) = l0;
                *(uint32_t*)(al + row1 * XROW_B + colb) = l1;
            }
    }
    __syncthreads();   // ao tiles ready

    // ---- Phase D: y = out_w @ ao + bias + residual -> direct gmem; BN via shfl ----
    {
        const uint32_t ahi_u32 = SB;
        const uint32_t alo_u32 = SB + XLO_BYTE;
        float acc[2][16];
#pragma unroll
        for (int m = 0; m < 2; m++)
#pragma unroll
            for (int j = 0; j < 16; j++) acc[m][j] = 0.0f;
#pragma unroll
        for (int term = 0; term < 3; term++) {
            const int termA = (term == 2) ? 1 : 0;
            const uint32_t xbase = (term == 1) ? alo_u32 : ahi_u32;
#pragma unroll
            for (int ks = 0; ks < 8; ks++) {
                uint32_t baddr = xbase + ntb * XROW_B + ks * 32 + khb;
                uint32_t b0, b1, b2, b3, b4, b5, b6, b7;
                LDSM_X4(b0, b1, b2, b3, baddr);
                LDSM_X4(b4, b5, b6, b7, baddr + 16 * XROW_B);
#pragma unroll
                for (int m = 0; m < 2; m++) {
                    int mt = wid * 2 + m;
                    uint4 a = g_ofrag[((termA * 8 + mt) * 8 + ks) * 32 + lane];
                    uint32_t au[4] = {a.x, a.y, a.z, a.w};
                    mma_a(acc[m] + 0,  au, b0, b1);
                    mma_a(acc[m] + 4,  au, b2, b3);
                    mma_a(acc[m] + 8,  au, b4, b5);
                    mma_a(acc[m] + 12, au, b6, b7);
                }
            }
        }
#pragma unroll
        for (int m = 0; m < 2; m++) {
            int mt = wid * 2 + m;
            int r0 = mt * 16 + g, r1 = r0 + 8;
            float bias0 = out_b[r0], bias1 = out_b[r1];
            float s1a = 0.0f, s2a = 0.0f, s1b = 0.0f, s2b = 0.0f;
#pragma unroll
            for (int nt = 0; nt < 4; nt++) {
                int nc = nt * 8 + 2 * cg;
                float2 x0 = *(const float2*)(xb + r0 * 32 + nc);
                float2 x1 = *(const float2*)(xb + r1 * 32 + nc);
                float y00 = acc[m][nt*4+0] + bias0 + x0.x;
                float y01 = acc[m][nt*4+1] + bias0 + x0.y;
                float y10 = acc[m][nt*4+2] + bias1 + x1.x;
                float y11 = acc[m][nt*4+3] + bias1 + x1.y;
                *(float2*)(ob2g + r0 * 32 + nc) = make_float2(y00, y01);
                *(float2*)(ob2g + r1 * 32 + nc) = make_float2(y10, y11);
                s1a += y00 + y01; s2a = fmaf(y00, y00, s2a); s2a = fmaf(y01, y01, s2a);
                s1b += y10 + y11; s2b = fmaf(y10, y10, s2b); s2b = fmaf(y11, y11, s2b);
            }
            // reduce over the 4 cg-lanes (lane bits 0,1)
            s1a += __shfl_xor_sync(0xffffffffu, s1a, 1);
            s1a += __shfl_xor_sync(0xffffffffu, s1a, 2);
            s2a += __shfl_xor_sync(0xffffffffu, s2a, 1);
            s2a += __shfl_xor_sync(0xffffffffu, s2a, 2);
            s1b += __shfl_xor_sync(0xffffffffu, s1b, 1);
            s1b += __shfl_xor_sync(0xffffffffu, s1b, 2);
            s2b += __shfl_xor_sync(0xffffffffu, s2b, 1);
            s2b += __shfl_xor_sync(0xffffffffu, s2b, 2);
            if (cg == 0) {
                atomicAdd(&g_bn_sum[r0], (double)s1a);
                atomicAdd(&g_bn_sqs[r0], (double)s2a);
                atomicAdd(&g_bn_sum[r1], (double)s1b);
                atomicAdd(&g_bn_sqs[r1], (double)s2b);
            }
        }
    }
}

__global__ void bn_finalize(const float* __restrict__ gamma,
                            const float* __restrict__ beta) {
    int c = threadIdx.x;
    const double cnt = (double)BATCH * NB;
    double mean = g_bn_sum[c] / cnt;
    double var  = g_bn_sqs[c] / cnt - mean * mean;
    double inv  = 1.0 / sqrt(var + 1e-5);
    double g = (double)gamma[c] * inv;
    g_bn_g[c] = (float)g;
    g_bn_b[c] = (float)((double)beta[c] - mean * g);
}

__global__ void bn_apply(float* __restrict__ out) {
    int i = blockIdx.x * blockDim.x + threadIdx.x;
    float4 v = ((const float4*)out)[i];
    int c = (i >> 3) & 127;
    float g = g_bn_g[c], b = g_bn_b[c];
    v.x = fmaf(v.x, g, b);
    v.y = fmaf(v.y, g, b);
    v.z = fmaf(v.z, g, b);
    v.w = fmaf(v.w, g, b);
    ((float4*)out)[i] = v;
}

extern "C" void kernel_launch(void* const* d_in, const int* in_sizes, int n_in,
                              void* d_out, int out_size) {
    const float* x      = (const float*)d_in[0];
    const float* qkv_w  = (const float*)d_in[1];
    const float* qkv_b  = (const float*)d_in[2];
    const float* out_w  = (const float*)d_in[3];
    const float* out_b  = (const float*)d_in[4];
    const float* remb   = (const float*)d_in[5];
    const float* gamma  = (const float*)d_in[6];
    const float* beta   = (const float*)d_in[7];
    float* out = (float*)d_out;

    cudaFuncSetAttribute(attn_kernel, cudaFuncAttributeMaxDynamicSharedMemorySize,
                         SMEM_FLOATS * (int)sizeof(float));

    prep_kernel<<<192, 256>>>(qkv_w, out_w);
    attn_kernel<<<BATCH, 128, SMEM_FLOATS * sizeof(float)>>>(x, qkv_b, out_b, remb, out);
    bn_finalize<<<1, CH>>>(gamma, beta);
    bn_apply<<<(BATCH * CH * NB / 4) / 256, 256>>>(out);
}

// round 17
// speedup vs baseline: 1.2308x; 1.2308x over previous
#include <cuda_runtime.h>
#include <cuda_bf16.h>
#include <math.h>
#include <stdint.h>

#define BATCH 8192
#define CH 128
#define NB 32
#define NH 4
#define O3 384
#define ATT_SCALE 0.17677669529663687f  // 1/sqrt(32)

__device__ __forceinline__ uint32_t smem_u32(const void* p) {
    uint32_t a;
    asm("{ .reg .u64 t; cvta.to.shared.u64 t, %1; cvt.u32.u64 %0, t; }" : "=r"(a) : "l"(p));
    return a;
}
__device__ __forceinline__ void mma_a(float* acc, const uint32_t* a, uint32_t b0, uint32_t b1) {
    asm volatile(
        "mma.sync.aligned.m16n8k16.row.col.f32.bf16.bf16.f32 "
        "{%0,%1,%2,%3}, {%4,%5,%6,%7}, {%8,%9}, {%0,%1,%2,%3};"
        : "+f"(acc[0]), "+f"(acc[1]), "+f"(acc[2]), "+f"(acc[3])
        : "r"(a[0]), "r"(a[1]), "r"(a[2]), "r"(a[3]), "r"(b0), "r"(b1));
}
__device__ __forceinline__ uint32_t cvtbf2(float hi, float lo) {
    uint32_t r; asm("cvt.rn.bf16x2.f32 %0, %1, %2;" : "=r"(r) : "f"(hi), "f"(lo)); return r;
}
__device__ __forceinline__ float bf_lo_f(uint32_t w) { return __uint_as_float(w << 16); }
__device__ __forceinline__ float bf_hi_f(uint32_t w) { return __uint_as_float(w & 0xffff0000u); }
#define LDSM_X4(r0,r1,r2,r3,addr) \
    asm volatile("ldmatrix.sync.aligned.m8n8.x4.shared.b16 {%0,%1,%2,%3}, [%4];" \
        : "=r"(r0), "=r"(r1), "=r"(r2), "=r"(r3) : "r"(addr))
#define LDSM_X4T(r0,r1,r2,r3,addr) \
    asm volatile("ldmatrix.sync.aligned.m8n8.x4.trans.shared.b16 {%0,%1,%2,%3}, [%4];" \
        : "=r"(r0), "=r"(r1), "=r"(r2), "=r"(r3) : "r"(addr))

// ---- device scratch ----
__device__ uint4  g_wfrag[2 * 24 * 8 * 32];   // qkv_w fragments [term][mt][ks][lane]
__device__ uint4  g_ofrag[2 * 8 * 8 * 32];    // out_w fragments
__device__ double g_bn_sum[CH];
__device__ double g_bn_sqs[CH];
__device__ float  g_bn_g[CH];
__device__ float  g_bn_b[CH];

__device__ __forceinline__ uint32_t bf16pair(float w0, float w1, int lo_term) {
    __nv_bfloat16 h0 = __float2bfloat16_rn(w0);
    __nv_bfloat16 h1 = __float2bfloat16_rn(w1);
    if (lo_term) {
        h0 = __float2bfloat16_rn(w0 - __bfloat162float(h0));
        h1 = __float2bfloat16_rn(w1 - __bfloat162float(h1));
    }
    return ((uint32_t)__bfloat16_as_ushort(h1) << 16) | __bfloat16_as_ushort(h0);
}

__global__ void prep_kernel(const float* __restrict__ qkv_w,
                            const float* __restrict__ out_w) {
    int i = blockIdx.x * blockDim.x + threadIdx.x;
    if (i < 2 * 24 * 8 * 32) {
        int lane = i & 31, ks = (i >> 5) & 7, mt = (i >> 8) % 24, term = i / (24 * 8 * 32);
        int g = lane >> 2, cg = lane & 3;
        int r0 = mt * 16 + g, r1 = r0 + 8;
        int c0 = ks * 16 + 2 * cg, c1 = c0 + 8;
        uint4 f;
        f.x = bf16pair(qkv_w[r0 * CH + c0], qkv_w[r0 * CH + c0 + 1], term);
        f.y = bf16pair(qkv_w[r1 * CH + c0], qkv_w[r1 * CH + c0 + 1], term);
        f.z = bf16pair(qkv_w[r0 * CH + c1], qkv_w[r0 * CH + c1 + 1], term);
        f.w = bf16pair(qkv_w[r1 * CH + c1], qkv_w[r1 * CH + c1 + 1], term);
        g_wfrag[i] = f;
    }
    if (i < 2 * 8 * 8 * 32) {
        int lane = i & 31, ks = (i >> 5) & 7, mt = (i >> 8) & 7, term = i / (8 * 8 * 32);
        int g = lane >> 2, cg = lane & 3;
        int r0 = mt * 16 + g, r1 = r0 + 8;
        int c0 = ks * 16 + 2 * cg, c1 = c0 + 8;
        uint4 f;
        f.x = bf16pair(out_w[r0 * CH + c0], out_w[r0 * CH + c0 + 1], term);
        f.y = bf16pair(out_w[r1 * CH + c0], out_w[r1 * CH + c0 + 1], term);
        f.z = bf16pair(out_w[r0 * CH + c1], out_w[r0 * CH + c1 + 1], term);
        f.w = bf16pair(out_w[r1 * CH + c1], out_w[r1 * CH + c1 + 1], term);
        g_ofrag[i] = f;
    }
    if (i < CH) { g_bn_sum[i] = 0.0; g_bn_sqs[i] = 0.0; }
}

// smem map (bytes), 68,608 total -> 3 CTAs/SM:
//  [0..18431]      region0: x hi/lo tiles [32][136]bf16 (A) -> ao hi/lo tiles (C/D)
//  [18432..67583]  qkvt: qh,ql,kh,kl,vh,vl each [128][32]bf16 -> ys [128][36] f32 (D)
//  [67584..68591]  rp [4][63] f32
#define XLO_BYTE 8704
#define XROW_B   272
#define QT_BYTE  18432
#define MATK     16384
#define MATV     32768
#define LO_OFF   8192
#define RP_FLOAT 16896
#define SMEM_FLOATS 17152

__global__ void __launch_bounds__(128, 3)
attn_kernel(const float* __restrict__ x,
            const float* __restrict__ qkv_b,
            const float* __restrict__ out_b,
            const float* __restrict__ remb,
            float* __restrict__ out) {
    extern __shared__ float sm[];
    float* ys = sm + 4608;             // over dead qkvt region (after Phase C)
    float* rp = sm + RP_FLOAT;

    const int tid  = threadIdx.x;
    const int lane = tid & 31;
    const int wid  = tid >> 5;
    const int b    = blockIdx.x;
    const float* xb = x + (size_t)b * (CH * NB);

    const int g  = lane >> 2, tg = lane & 3, cg = tg;
    const int sub = lane >> 3, i7 = lane & 7;
    const int ntb = ((sub >> 1) & 1) * 8 + i7;   // plain ldmatrix row offset
    const int khb = (sub & 1) * 16;              // plain ldmatrix byte-col offset
    const int qa_d = ((sub >> 1) & 1) * 8 + i7;  // trans-A: memory row (d)
    const int qa_n = (sub & 1) * 8;              // trans-A: memory col (n)
    const int kb_d = (sub & 1) * 8 + i7;         // trans-B: memory row (d)
    const int kb_m = ((sub >> 1) & 1) * 8;       // trans-B: memory col (m)

    const uint32_t SB = smem_u32(sm);

    // ---- convert x[b] -> bf16 hi/lo tiles [n][136] in region0 (R13 path) ----
    {
        __nv_bfloat16* xh = (__nv_bfloat16*)sm;
        __nv_bfloat16* xl = (__nv_bfloat16*)((char*)sm + XLO_BYTE);
        const float4* xg = (const float4*)xb;
#pragma unroll
        for (int k = 0; k < 8; k++) {
            int f = tid + k * 128;
            float4 v = xg[f];
            int c = f >> 3;
            int n0 = (f & 7) * 4;
            float vv[4] = {v.x, v.y, v.z, v.w};
#pragma unroll
            for (int j = 0; j < 4; j++) {
                float w = vv[j];
                __nv_bfloat16 h = __float2bfloat16_rn(w);
                __nv_bfloat16 l = __float2bfloat16_rn(w - __bfloat162float(h));
                xh[(n0 + j) * 136 + c] = h;
                xl[(n0 + j) * 136 + c] = l;
            }
        }
    }
    for (int i = tid; i < (2 * NB - 1) * NH; i += 128) {
        int p = i >> 2, h = i & 3;
        rp[h * 63 + p] = remb[i];
    }
    __syncthreads();

    // ---- Phase A: qkv = W @ x ; 2-mt blocks share B fragments ----
    {
        const uint32_t xhi_u32 = SB, xlo_u32 = SB + XLO_BYTE;
#pragma unroll
        for (int blk = 0; blk < 3; blk++) {
            float acc[2][16];
#pragma unroll
            for (int m = 0; m < 2; m++)
#pragma unroll
                for (int j = 0; j < 16; j++) acc[m][j] = 0.0f;
#pragma unroll
            for (int term = 0; term < 3; term++) {
                const int termA = (term == 2) ? 1 : 0;
                const uint32_t xbase = (term == 1) ? xlo_u32 : xhi_u32;
#pragma unroll
                for (int ks = 0; ks < 8; ks++) {
                    uint32_t baddr = xbase + ntb * XROW_B + ks * 32 + khb;
                    uint32_t b0, b1, b2, b3, b4, b5, b6, b7;
                    LDSM_X4(b0, b1, b2, b3, baddr);
                    LDSM_X4(b4, b5, b6, b7, baddr + 16 * XROW_B);
#pragma unroll
                    for (int m = 0; m < 2; m++) {
                        int mt = wid * 6 + blk * 2 + m;
                        uint4 a = g_wfrag[((termA * 24 + mt) * 8 + ks) * 32 + lane];
                        uint32_t au[4] = {a.x, a.y, a.z, a.w};
                        mma_a(acc[m] + 0,  au, b0, b1);
                        mma_a(acc[m] + 4,  au, b2, b3);
                        mma_a(acc[m] + 8,  au, b4, b5);
                        mma_a(acc[m] + 12, au, b6, b7);
                    }
                }
            }
#pragma unroll
            for (int m = 0; m < 2; m++) {
                int mt = wid * 6 + blk * 2 + m;
                int r0 = mt * 16 + g, r1 = r0 + 8;
                float bias0 = qkv_b[r0], bias1 = qkv_b[r1];
                int mat = r0 >> 7;
                char* hb0 = (char*)sm + QT_BYTE + mat * 16384 + (r0 & 127) * 64;
                char* hb1 = (char*)sm + QT_BYTE + mat * 16384 + (r1 & 127) * 64;
#pragma unroll
                for (int nt = 0; nt < 4; nt++) {
                    int nc2 = (nt * 8 + 2 * cg) * 2;
                    float v00 = acc[m][nt*4+0] + bias0, v01 = acc[m][nt*4+1] + bias0;
                    float v10 = acc[m][nt*4+2] + bias1, v11 = acc[m][nt*4+3] + bias1;
                    uint32_t h0 = cvtbf2(v01, v00);
                    uint32_t h1 = cvtbf2(v11, v10);
                    *(uint32_t*)(hb0 + nc2) = h0;
                    *(uint32_t*)(hb1 + nc2) = h1;
                    uint32_t l0 = cvtbf2(v01 - bf_hi_f(h0), v00 - bf_lo_f(h0));
                    uint32_t l1 = cvtbf2(v11 - bf_hi_f(h1), v10 - bf_lo_f(h1));
                    *(uint32_t*)(hb0 + LO_OFF + nc2) = l0;
                    *(uint32_t*)(hb1 + LO_OFF + nc2) = l1;
                }
            }
        }
    }
    __syncthreads();   // qkv tiles ready; x tiles dead

    // ---- Phase B: S = Q^T K per head via mma (3-term bf16-split) ----
    float sa[2][4][4];
#pragma unroll
    for (int a1 = 0; a1 < 2; a1++)
#pragma unroll
        for (int a2 = 0; a2 < 4; a2++)
#pragma unroll
            for (int a3 = 0; a3 < 4; a3++) sa[a1][a2][a3] = 0.0f;
    {
        const int dgb = wid * 32;
        const uint32_t qb0 = SB + QT_BYTE;
        const uint32_t kb0 = SB + QT_BYTE + MATK;
#pragma unroll
        for (int term = 0; term < 3; term++) {
            const uint32_t qm = qb0 + ((term == 2) ? LO_OFF : 0);
            const uint32_t km = kb0 + ((term == 1) ? LO_OFF : 0);
#pragma unroll
            for (int kb = 0; kb < 32; kb += 16) {
                uint32_t aQ[2][4], bK[2][4];
#pragma unroll
                for (int nb2 = 0; nb2 < 2; nb2++) {
                    uint32_t ad = qm + (dgb + kb + qa_d) * 64 + (nb2 * 16 + qa_n) * 2;
                    LDSM_X4T(aQ[nb2][0], aQ[nb2][1], aQ[nb2][2], aQ[nb2][3], ad);
                }
#pragma unroll
                for (int mb2 = 0; mb2 < 2; mb2++) {
                    uint32_t ad = km + (dgb + kb + kb_d) * 64 + (mb2 * 16 + kb_m) * 2;
                    LDSM_X4T(bK[mb2][0], bK[mb2][1], bK[mb2][2], bK[mb2][3], ad);
                }
#pragma unroll
                for (int nb = 0; nb < 2; nb++) {
                    mma_a(sa[nb][0], aQ[nb], bK[0][0], bK[0][1]);
                    mma_a(sa[nb][1], aQ[nb], bK[0][2], bK[0][3]);
                    mma_a(sa[nb][2], aQ[nb], bK[1][0], bK[1][1]);
                    mma_a(sa[nb][3], aQ[nb], bK[1][2], bK[1][3]);
                }
            }
        }
    }

    // ---- softmax on fragments ----
    {
#pragma unroll
        for (int nb = 0; nb < 2; nb++)
#pragma unroll
            for (int nt = 0; nt < 4; nt++)
#pragma unroll
                for (int j = 0; j < 4; j++) {
                    int row = nb * 16 + g + (j >> 1) * 8;
                    int m = nt * 8 + 2 * tg + (j & 1);
                    sa[nb][nt][j] = fmaf(sa[nb][nt][j], ATT_SCALE,
                                         rp[wid * 63 + (m - row + NB - 1)]);
                }
        float mx[4], sme[4];
#pragma unroll
        for (int k = 0; k < 4; k++) {
            int nb = k >> 1, jo = (k & 1) * 2;
            float m0 = -1e30f;
#pragma unroll
            for (int nt = 0; nt < 4; nt++)
                m0 = fmaxf(m0, fmaxf(sa[nb][nt][jo], sa[nb][nt][jo + 1]));
            mx[k] = m0;
        }
#pragma unroll
        for (int k = 0; k < 4; k++) {
            mx[k] = fmaxf(mx[k], __shfl_xor_sync(0xffffffffu, mx[k], 1));
            mx[k] = fmaxf(mx[k], __shfl_xor_sync(0xffffffffu, mx[k], 2));
        }
#pragma unroll
        for (int k = 0; k < 4; k++) {
            int nb = k >> 1, jo = (k & 1) * 2;
            float s = 0.0f;
#pragma unroll
            for (int nt = 0; nt < 4; nt++) {
                float e0 = __expf(sa[nb][nt][jo]     - mx[k]);
                float e1 = __expf(sa[nb][nt][jo + 1] - mx[k]);
                sa[nb][nt][jo] = e0; sa[nb][nt][jo + 1] = e1;
                s += e0 + e1;
            }
            sme[k] = s;
        }
#pragma unroll
        for (int k = 0; k < 4; k++) {
            sme[k] += __shfl_xor_sync(0xffffffffu, sme[k], 1);
            sme[k] += __shfl_xor_sync(0xffffffffu, sme[k], 2);
            sme[k] = 1.0f / sme[k];
        }
#pragma unroll
        for (int k = 0; k < 4; k++) {
            int nb = k >> 1, jo = (k & 1) * 2;
#pragma unroll
            for (int nt = 0; nt < 4; nt++) {
                sa[nb][nt][jo]     *= sme[k];
                sa[nb][nt][jo + 1] *= sme[k];
            }
        }
    }

    // ---- Phase C: O = P V via mma; P fragments direct (hi/lo split) ----
    {
        uint32_t ph[2][2][4], pl[2][2][4];
#pragma unroll
        for (int nb = 0; nb < 2; nb++)
#pragma unroll
            for (int mk = 0; mk < 2; mk++) {
                const float* p0 = sa[nb][2 * mk];
                const float* p1 = sa[nb][2 * mk + 1];
                uint32_t h;
                h = cvtbf2(p0[1], p0[0]); ph[nb][mk][0] = h;
                pl[nb][mk][0] = cvtbf2(p0[1] - bf_hi_f(h), p0[0] - bf_lo_f(h));
                h = cvtbf2(p0[3], p0[2]); ph[nb][mk][1] = h;
                pl[nb][mk][1] = cvtbf2(p0[3] - bf_hi_f(h), p0[2] - bf_lo_f(h));
                h = cvtbf2(p1[1], p1[0]); ph[nb][mk][2] = h;
                pl[nb][mk][2] = cvtbf2(p1[1] - bf_hi_f(h), p1[0] - bf_lo_f(h));
                h = cvtbf2(p1[3], p1[2]); ph[nb][mk][3] = h;
                pl[nb][mk][3] = cvtbf2(p1[3] - bf_hi_f(h), p1[2] - bf_lo_f(h));
            }
        float oa[2][4][4];
#pragma unroll
        for (int a1 = 0; a1 < 2; a1++)
#pragma unroll
            for (int a2 = 0; a2 < 4; a2++)
#pragma unroll
                for (int a3 = 0; a3 < 4; a3++) oa[a1][a2][a3] = 0.0f;

        const int dgb = wid * 32;
        const uint32_t vb0 = SB + QT_BYTE + MATV;
#pragma unroll
        for (int term = 0; term < 3; term++) {
            const int useL = (term == 2);
            const uint32_t vm = vb0 + ((term == 1) ? LO_OFF : 0);
#pragma unroll
            for (int mk = 0; mk < 2; mk++) {
                uint32_t bV[2][4];
#pragma unroll
                for (int dvb = 0; dvb < 2; dvb++) {
                    uint32_t ad = vm + (dgb + dvb * 16 + ntb) * 64 + mk * 32 + khb;
                    LDSM_X4(bV[dvb][0], bV[dvb][1], bV[dvb][2], bV[dvb][3], ad);
                }
#pragma unroll
                for (int nb = 0; nb < 2; nb++) {
                    const uint32_t* ap = useL ? pl[nb][mk] : ph[nb][mk];
                    mma_a(oa[nb][0], ap, bV[0][0], bV[0][1]);
                    mma_a(oa[nb][1], ap, bV[0][2], bV[0][3]);
                    mma_a(oa[nb][2], ap, bV[1][0], bV[1][1]);
                    mma_a(oa[nb][3], ap, bV[1][2], bV[1][3]);
                }
            }
        }
        // epilogue: write ao bf16 hi/lo tiles [n][136] (region0; x tiles dead)
        char* ah = (char*)sm;
        char* al = (char*)sm + XLO_BYTE;
#pragma unroll
        for (int nb = 0; nb < 2; nb++)
#pragma unroll
            for (int dvt = 0; dvt < 4; dvt++) {
                int row0 = nb * 16 + g, row1 = row0 + 8;
                int colb = (wid * 32 + dvt * 8 + 2 * tg) * 2;
                float d0 = oa[nb][dvt][0], d1 = oa[nb][dvt][1];
                float d2 = oa[nb][dvt][2], d3 = oa[nb][dvt][3];
                uint32_t h0 = cvtbf2(d1, d0), h1 = cvtbf2(d3, d2);
                *(uint32_t*)(ah + row0 * XROW_B + colb) = h0;
                *(uint32_t*)(ah + row1 * XROW_B + colb) = h1;
                uint32_t l0 = cvtbf2(d1 - bf_hi_f(h0), d0 - bf_lo_f(h0));
                uint32_t l1 = cvtbf2(d3 - bf_hi_f(h1), d2 - bf_lo_f(h1));
                *(uint32_t*)(al + row0 * XROW_B + colb) = l0;
                *(uint32_t*)(al + row1 * XROW_B + colb) = l1;
            }
    }
    __syncthreads();   // ao tiles ready; qkvt dead -> ys region

    // ---- Phase D: y = out_w @ ao via mma + bias + residual -> ys (R13 epilogue) ----
    {
        const uint32_t ahi_u32 = SB;
        const uint32_t alo_u32 = SB + XLO_BYTE;
        float acc[2][16];
#pragma unroll
        for (int m = 0; m < 2; m++)
#pragma unroll
            for (int j = 0; j < 16; j++) acc[m][j] = 0.0f;
#pragma unroll
        for (int term = 0; term < 3; term++) {
            const int termA = (term == 2) ? 1 : 0;
            const uint32_t xbase = (term == 1) ? alo_u32 : ahi_u32;
#pragma unroll
            for (int ks = 0; ks < 8; ks++) {
                uint32_t baddr = xbase + ntb * XROW_B + ks * 32 + khb;
                uint32_t b0, b1, b2, b3, b4, b5, b6, b7;
                LDSM_X4(b0, b1, b2, b3, baddr);
                LDSM_X4(b4, b5, b6, b7, baddr + 16 * XROW_B);
#pragma unroll
                for (int m = 0; m < 2; m++) {
                    int mt = wid * 2 + m;
                    uint4 a = g_ofrag[((termA * 8 + mt) * 8 + ks) * 32 + lane];
                    uint32_t au[4] = {a.x, a.y, a.z, a.w};
                    mma_a(acc[m] + 0,  au, b0, b1);
                    mma_a(acc[m] + 4,  au, b2, b3);
                    mma_a(acc[m] + 8,  au, b4, b5);
                    mma_a(acc[m] + 12, au, b6, b7);
                }
            }
        }
#pragma unroll
        for (int m = 0; m < 2; m++) {
            int mt = wid * 2 + m;
            int r0 = mt * 16 + g, r1 = r0 + 8;
            float bias0 = out_b[r0], bias1 = out_b[r1];
#pragma unroll
            for (int nt = 0; nt < 4; nt++) {
                int nc = nt * 8 + 2 * cg;
                float2 x0 = *(const float2*)(xb + r0 * 32 + nc);
                float2 x1 = *(const float2*)(xb + r1 * 32 + nc);
                *(float2*)(ys + r0 * 36 + nc) =
                    make_float2(acc[m][nt*4+0] + bias0 + x0.x, acc[m][nt*4+1] + bias0 + x0.y);
                *(float2*)(ys + r1 * 36 + nc) =
                    make_float2(acc[m][nt*4+2] + bias1 + x1.x, acc[m][nt*4+3] + bias1 + x1.y);
            }
        }
    }
    __syncthreads();

    // ---- BN partial stats (thread = channel) ----
    {
        int o = tid;
        float s1 = 0.0f, s2 = 0.0f;
        const float4* yr = (const float4*)(ys + o * 36);
#pragma unroll
        for (int j = 0; j < 8; j++) {
            float4 v = yr[j];
            s1 += (v.x + v.y) + (v.z + v.w);
            s2 = fmaf(v.x, v.x, s2); s2 = fmaf(v.y, v.y, s2);
            s2 = fmaf(v.z, v.z, s2); s2 = fmaf(v.w, v.w, s2);
        }
        atomicAdd(&g_bn_sum[o], (double)s1);
        atomicAdd(&g_bn_sqs[o], (double)s2);
    }

    // ---- coalesced write of pre-BN y to gmem ----
    float4* og = (float4*)(out + (size_t)b * (CH * NB));
#pragma unroll
    for (int k = 0; k < 8; k++) {
        int f = tid + k * 128;
        int c = f >> 3, n4 = f & 7;
        og[f] = *(const float4*)(ys + c * 36 + n4 * 4);
    }
}

__global__ void bn_finalize(const float* __restrict__ gamma,
                            const float* __restrict__ beta) {
    int c = threadIdx.x;
    const double cnt = (double)BATCH * NB;
    double mean = g_bn_sum[c] / cnt;
    double var  = g_bn_sqs[c] / cnt - mean * mean;
    double inv  = 1.0 / sqrt(var + 1e-5);
    double g = (double)gamma[c] * inv;
    g_bn_g[c] = (float)g;
    g_bn_b[c] = (float)((double)beta[c] - mean * g);
}

__global__ void bn_apply(float* __restrict__ out) {
    int i = blockIdx.x * blockDim.x + threadIdx.x;
    float4 v = ((const float4*)out)[i];
    int c = (i >> 3) & 127;
    float g = g_bn_g[c], b = g_bn_b[c];
    v.x = fmaf(v.x, g, b);
    v.y = fmaf(v.y, g, b);
    v.z = fmaf(v.z, g, b);
    v.w = fmaf(v.w, g, b);
    ((float4*)out)[i] = v;
}

extern "C" void kernel_launch(void* const* d_in, const int* in_sizes, int n_in,
                              void* d_out, int out_size) {
    const float* x      = (const float*)d_in[0];
    const float* qkv_w  = (const float*)d_in[1];
    const float* qkv_b  = (const float*)d_in[2];
    const float* out_w  = (const float*)d_in[3];
    const float* out_b  = (const float*)d_in[4];
    const float* remb   = (const float*)d_in[5];
    const float* gamma  = (const float*)d_in[6];
    const float* beta   = (const float*)d_in[7];
    float* out = (float*)d_out;

    cudaFuncSetAttribute(attn_kernel, cudaFuncAttributeMaxDynamicSharedMemorySize,
                         SMEM_FLOATS * (int)sizeof(float));

    prep_kernel<<<192, 256>>>(qkv_w, out_w);
    attn_kernel<<<BATCH, 128, SMEM_FLOATS * sizeof(float)>>>(x, qkv_b, out_b, remb, out);
    bn_finalize<<<1, CH>>>(gamma, beta);
    bn_apply<<<(BATCH * CH * NB / 4) / 256, 256>>>(out);
}